// round 6
// baseline (speedup 1.0000x reference)
#include <cuda_runtime.h>
#include <cstdint>
#include <math.h>

#define NIR 10
#define EPS2 1e-12f
#define INV_SQRT10 0.31622776601683794f

#define TABN 128
#define RMAX 8.0f
#define DELTA (RMAX / (float)TABN)
#define INV_DELTA ((float)TABN / RMAX)

// coefficient table: h_v(r) ~= a_v + b_v*r on interval k.
// row layout: 7 x float4; j in 0..4 holds (a_{2j}, b_{2j}, a_{2j+1}, b_{2j+1}); j=5,6 pad.
// row stride = 112B, gcd(7,8)=1 -> uniform bank spread for random k.
__device__ __align__(16) float4 g_tab[TABN][7];

static __device__ __forceinline__ float ex2f(float x){ float r; asm("ex2.approx.f32 %0, %1;" : "=f"(r) : "f"(x)); return r; }
static __device__ __forceinline__ float rcpf(float x){ float r; asm("rcp.approx.f32 %0, %1;" : "=f"(r) : "f"(x)); return r; }
static __device__ __forceinline__ float rsqf(float x){ float r; asm("rsqrt.approx.f32 %0, %1;" : "=f"(r) : "f"(x)); return r; }
static __device__ __forceinline__ float sqrtaf(float x){ float r; asm("sqrt.approx.f32 %0, %1;" : "=f"(r) : "f"(x)); return r; }

static __device__ __forceinline__ float tanh_fast(float z){
    float e = ex2f(z * 2.8853900817779268f);
    float r = rcpf(e + 1.0f);
    return fmaf(-2.0f, r, 1.0f);
}

static __device__ __forceinline__ uint64_t pack2(float lo, float hi){
    uint64_t r; asm("mov.b64 %0, {%1, %2};" : "=l"(r) : "f"(lo), "f"(hi)); return r;
}
static __device__ __forceinline__ float2 unpack2(uint64_t v){
    float2 f; asm("mov.b64 {%0, %1}, %2;" : "=f"(f.x), "=f"(f.y) : "l"(v)); return f;
}
static __device__ __forceinline__ uint64_t fma2(uint64_t a, uint64_t b, uint64_t c){
    uint64_t d; asm("fma.rn.f32x2 %0, %1, %2, %3;" : "=l"(d) : "l"(a), "l"(b), "l"(c)); return d;
}
static __device__ __forceinline__ uint64_t lo64(float4 w){ return pack2(w.x, w.y); }
static __device__ __forceinline__ uint64_t hi64(float4 w){ return pack2(w.z, w.w); }

// ---------------- table build ----------------
static __device__ void eval_h(float r,
                              const float* __restrict__ lw1, const float* __restrict__ nb1,
                              const float* __restrict__ lw2, const float* __restrict__ nb2,
                              const float* __restrict__ wf, float* h)
{
    float n2 = r * r;
    float g[NIR];
    #pragma unroll
    for (int u = 0; u < NIR; u++){
        float a   = lw1[u];
        float arg = fmaf(a * a, n2, EPS2);
        float inv = rsqf(arg);
        float nrm = arg * inv;
        g[u] = tanh_fast(nrm + nb1[u]) * inv;
    }
    #pragma unroll
    for (int v = 0; v < NIR; v++){
        float c = 0.0f;
        #pragma unroll
        for (int u = 0; u < NIR; u++)
            c = fmaf(g[u] * lw1[u], lw2[u * NIR + v], c);
        c *= INV_SQRT10;
        float arg = fmaf(c * c, n2, EPS2);
        float inv = rsqf(arg);
        float nrm = arg * inv;
        float scal2 = tanh_fast(nrm + nb2[v]) * inv;
        h[v] = c * scal2 * wf[v] * INV_SQRT10;
    }
}

__global__ void build_table(const float* __restrict__ lw1, const float* __restrict__ nb1,
                            const float* __restrict__ lw2, const float* __restrict__ nb2,
                            const float* __restrict__ wf)
{
    int k = threadIdx.x;
    if (k >= TABN) return;
    float r0 = (float)k * DELTA;
    float h0[NIR], h1[NIR];
    eval_h(r0,         lw1, nb1, lw2, nb2, wf, h0);
    eval_h(r0 + DELTA, lw1, nb1, lw2, nb2, wf, h1);
    #pragma unroll
    for (int j = 0; j < 5; j++){
        float bb0 = (h1[2*j]   - h0[2*j])   * INV_DELTA;
        float bb1 = (h1[2*j+1] - h0[2*j+1]) * INV_DELTA;
        float aa0 = fmaf(-bb0, r0, h0[2*j]);
        float aa1 = fmaf(-bb1, r0, h0[2*j+1]);
        g_tab[k][j] = make_float4(aa0, bb0, aa1, bb1);
    }
    g_tab[k][5] = make_float4(0.f, 0.f, 0.f, 0.f);
    g_tab[k][6] = make_float4(0.f, 0.f, 0.f, 0.f);
}

// ---------------- main kernel: 2 warps per batch, 4 elems/lane, 4 blocks/SM ----------------
__global__ __launch_bounds__(128, 4) void trq_2b_kernel(
    const float* __restrict__ v1b,   // (B,3)
    const float* __restrict__ invar, // (B,P,2)
    const float* __restrict__ vec2,  // (B,P,6)
    const float* __restrict__ W1,    // (2,10)
    const float* __restrict__ b1,    // (10)
    const float* __restrict__ W2,    // (10,10)
    const float* __restrict__ b2,    // (10)
    float* __restrict__ out)         // (B,3)
{
    __shared__ __align__(16) float4 sTab[TABN][7];   // 14336 B
    __shared__ __align__(16) float4 sW2T[5][5];      // transposed pair layout
    __shared__ float sW1x[NIR], sW1y[NIR], sB1[NIR], sB2[NIR];
    __shared__ float red[4][3];

    const int tid = threadIdx.x;

    {
        const float4* src = &g_tab[0][0];
        float4* dst = &sTab[0][0];
        #pragma unroll
        for (int i = tid; i < TABN * 7; i += 128)
            dst[i] = src[i];
    }
    if (tid < 100){
        int u = tid / 10, v = tid % 10;
        reinterpret_cast<float*>(sW2T)[(v >> 1) * 20 + (u >> 1) * 4 + ((u & 1) << 1) + (v & 1)] = W2[tid];
    }
    if (tid < 10){
        sW1x[tid] = W1[tid];
        sW1y[tid] = W1[10 + tid];
        sB1[tid]  = b1[tid];
        sB2[tid]  = b2[tid];
    }
    __syncthreads();

    const int w    = tid >> 5;       // 0..3
    const int lane = tid & 31;
    const int wp   = w >> 1;         // warp pair -> batch within block
    const int h    = w & 1;          // half of the 256 elements
    const int b    = blockIdx.x * 2 + wp;

    const size_t e0 = (size_t)b * 256 + h * 128 + lane;
    const float2* ivp = reinterpret_cast<const float2*>(invar) + e0;
    const float*  vb  = vec2 + e0 * 6;

    // ---- front-batch this warp's 4 iterations of global loads ----
    float2 iv[4];
    float  vx[4];
    float2 vyz[4];
    #pragma unroll
    for (int i = 0; i < 4; i++){
        iv[i]  = ivp[i * 32];
        const float* vp = vb + i * 192;           // 32*6
        vx[i]  = vp[3];
        vyz[i] = *reinterpret_cast<const float2*>(vp + 4);
    }

    uint64_t b2d[5];
    #pragma unroll
    for (int j = 0; j < 5; j++) b2d[j] = pack2(sB2[2*j], sB2[2*j+1]);

    float tx = 0.f, ty = 0.f, tz = 0.f;

    #pragma unroll
    for (int i = 0; i < 4; i++){
        // y1 = relu(invar @ W1 + b1), duplicated into f32x2 lanes
        uint64_t y1d[NIR];
        #pragma unroll
        for (int u = 0; u < NIR; u++){
            float y = fmaxf(fmaf(iv[i].x, sW1x[u], fmaf(iv[i].y, sW1y[u], sB1[u])), 0.0f);
            y1d[u] = pack2(y, y);
        }

        // y2 = relu(y1 @ W2 + b2): 25 broadcast LDS.128 + 50 fma2
        uint64_t y2d[NIR];
        #pragma unroll
        for (int j = 0; j < 5; j++){
            uint64_t acc = b2d[j];
            #pragma unroll
            for (int uu = 0; uu < 5; uu++){
                float4 wq = sW2T[j][uu];
                acc = fma2(y1d[2*uu],   lo64(wq), acc);
                acc = fma2(y1d[2*uu+1], hi64(wq), acc);
            }
            float2 rr = unpack2(acc);
            float m0 = fmaxf(rr.x, 0.0f);
            float m1 = fmaxf(rr.y, 0.0f);
            y2d[2*j]   = pack2(m0, m0);
            y2d[2*j+1] = pack2(m1, m1);
        }

        // r = |v|, table row k, dot with (a,b) pairs
        const float n2 = fmaf(vx[i], vx[i], fmaf(vyz[i].x, vyz[i].x, vyz[i].y * vyz[i].y));
        const float r  = sqrtaf(n2);
        int k = (int)(r * INV_DELTA);
        k = (k > TABN - 1) ? (TABN - 1) : k;

        const float4* row = sTab[k];
        uint64_t acc = 0ull;
        #pragma unroll
        for (int j = 0; j < 5; j++){
            float4 t = row[j];
            acc = fma2(y2d[2*j],   lo64(t), acc);
            acc = fma2(y2d[2*j+1], hi64(t), acc);
        }
        float2 sab = unpack2(acc);
        const float S = fmaf(r, sab.y, sab.x);

        tx = fmaf(vx[i],    S, tx);
        ty = fmaf(vyz[i].x, S, ty);
        tz = fmaf(vyz[i].y, S, tz);
    }

    // warp reduction, then combine warp pairs via shared
    #pragma unroll
    for (int off = 16; off > 0; off >>= 1){
        tx += __shfl_down_sync(0xFFFFFFFFu, tx, off);
        ty += __shfl_down_sync(0xFFFFFFFFu, ty, off);
        tz += __shfl_down_sync(0xFFFFFFFFu, tz, off);
    }
    if (lane == 0){ red[w][0] = tx; red[w][1] = ty; red[w][2] = tz; }
    __syncthreads();

    if (tid < 2){
        const int bb = blockIdx.x * 2 + tid;
        const float sx = red[2*tid][0] + red[2*tid+1][0];
        const float sy = red[2*tid][1] + red[2*tid+1][1];
        const float sz = red[2*tid][2] + red[2*tid+1][2];
        const float a0 = v1b[bb*3+0], a1 = v1b[bb*3+1], a2 = v1b[bb*3+2];
        out[bb*3+0] = a1 * sz - a2 * sy;
        out[bb*3+1] = a2 * sx - a0 * sz;
        out[bb*3+2] = a0 * sy - a1 * sx;
    }
}

extern "C" void kernel_launch(void* const* d_in, const int* in_sizes, int n_in,
                              void* d_out, int out_size)
{
    const float* v1b   = (const float*)d_in[0];
    const float* invar = (const float*)d_in[1];
    const float* vec2  = (const float*)d_in[2];
    const float* W1    = (const float*)d_in[3];
    const float* b1    = (const float*)d_in[4];
    const float* W2    = (const float*)d_in[5];
    const float* b2    = (const float*)d_in[6];
    const float* lw1   = (const float*)d_in[7];
    const float* nb1   = (const float*)d_in[8];
    const float* lw2   = (const float*)d_in[9];
    const float* nb2   = (const float*)d_in[10];
    const float* wf    = (const float*)d_in[11];

    const int B = out_size / 3;   // 4096

    build_table<<<1, TABN>>>(lw1, nb1, lw2, nb2, wf);
    trq_2b_kernel<<<B / 2, 128>>>(v1b, invar, vec2, W1, b1, W2, b2, (float*)d_out);
}

// round 7
// speedup vs baseline: 1.9623x; 1.9623x over previous
#include <cuda_runtime.h>
#include <cstdint>
#include <math.h>

#define NIR 10
#define EPS2 1e-12f
#define INV_SQRT10 0.31622776601683794f

#define TABN 256
#define RMAX 8.0f
#define DELTA (RMAX / (float)TABN)
#define INV_DELTA ((float)TABN / RMAX)

// coefficient table: h_v(r) ~= a_v + b_v*r on interval k.
// row layout: 7 x float4; j in 0..4 holds (a_{2j}, b_{2j}, a_{2j+1}, b_{2j+1}); j=5,6 pad.
__device__ __align__(16) float4 g_tab[TABN][7];

static __device__ __forceinline__ float ex2f(float x){ float r; asm("ex2.approx.f32 %0, %1;" : "=f"(r) : "f"(x)); return r; }
static __device__ __forceinline__ float rcpf(float x){ float r; asm("rcp.approx.f32 %0, %1;" : "=f"(r) : "f"(x)); return r; }
static __device__ __forceinline__ float rsqf(float x){ float r; asm("rsqrt.approx.f32 %0, %1;" : "=f"(r) : "f"(x)); return r; }
static __device__ __forceinline__ float sqrtaf(float x){ float r; asm("sqrt.approx.f32 %0, %1;" : "=f"(r) : "f"(x)); return r; }

static __device__ __forceinline__ float tanh_fast(float z){
    float e = ex2f(z * 2.8853900817779268f);
    float r = rcpf(e + 1.0f);
    return fmaf(-2.0f, r, 1.0f);
}

static __device__ __forceinline__ uint64_t pack2(float lo, float hi){
    uint64_t r; asm("mov.b64 %0, {%1, %2};" : "=l"(r) : "f"(lo), "f"(hi)); return r;
}
static __device__ __forceinline__ float2 unpack2(uint64_t v){
    float2 f; asm("mov.b64 {%0, %1}, %2;" : "=f"(f.x), "=f"(f.y) : "l"(v)); return f;
}
static __device__ __forceinline__ uint64_t fma2(uint64_t a, uint64_t b, uint64_t c){
    uint64_t d; asm("fma.rn.f32x2 %0, %1, %2, %3;" : "=l"(d) : "l"(a), "l"(b), "l"(c)); return d;
}
static __device__ __forceinline__ uint64_t lo64(float4 w){ return pack2(w.x, w.y); }
static __device__ __forceinline__ uint64_t hi64(float4 w){ return pack2(w.z, w.w); }

// ---------------- table build ----------------
static __device__ void eval_h(float r,
                              const float* __restrict__ lw1, const float* __restrict__ nb1,
                              const float* __restrict__ lw2, const float* __restrict__ nb2,
                              const float* __restrict__ wf, float* h)
{
    float n2 = r * r;
    float g[NIR];
    #pragma unroll
    for (int u = 0; u < NIR; u++){
        float a   = lw1[u];
        float arg = fmaf(a * a, n2, EPS2);
        float inv = rsqf(arg);
        float nrm = arg * inv;
        g[u] = tanh_fast(nrm + nb1[u]) * inv;
    }
    #pragma unroll
    for (int v = 0; v < NIR; v++){
        float c = 0.0f;
        #pragma unroll
        for (int u = 0; u < NIR; u++)
            c = fmaf(g[u] * lw1[u], lw2[u * NIR + v], c);
        c *= INV_SQRT10;
        float arg = fmaf(c * c, n2, EPS2);
        float inv = rsqf(arg);
        float nrm = arg * inv;
        float scal2 = tanh_fast(nrm + nb2[v]) * inv;
        h[v] = c * scal2 * wf[v] * INV_SQRT10;
    }
}

__global__ void build_table(const float* __restrict__ lw1, const float* __restrict__ nb1,
                            const float* __restrict__ lw2, const float* __restrict__ nb2,
                            const float* __restrict__ wf)
{
    int k = blockIdx.x * blockDim.x + threadIdx.x;
    if (k >= TABN) return;
    float r0 = (float)k * DELTA;
    float h0[NIR], h1[NIR];
    eval_h(r0,         lw1, nb1, lw2, nb2, wf, h0);
    eval_h(r0 + DELTA, lw1, nb1, lw2, nb2, wf, h1);
    #pragma unroll
    for (int j = 0; j < 5; j++){
        float bb0 = (h1[2*j]   - h0[2*j])   * INV_DELTA;
        float bb1 = (h1[2*j+1] - h0[2*j+1]) * INV_DELTA;
        float aa0 = fmaf(-bb0, r0, h0[2*j]);
        float aa1 = fmaf(-bb1, r0, h0[2*j+1]);
        g_tab[k][j] = make_float4(aa0, bb0, aa1, bb1);
    }
    g_tab[k][5] = make_float4(0.f, 0.f, 0.f, 0.f);
    g_tab[k][6] = make_float4(0.f, 0.f, 0.f, 0.f);
}

// ---------------- main kernel: warp-per-batch, f32x2, 2 blocks/SM ----------------
__global__ __launch_bounds__(256, 2) void trq_2b_kernel(
    const float* __restrict__ v1b,   // (B,3)
    const float* __restrict__ invar, // (B,P,2)
    const float* __restrict__ vec2,  // (B,P,6)
    const float* __restrict__ W1,    // (2,10)
    const float* __restrict__ b1,    // (10)
    const float* __restrict__ W2,    // (10,10)
    const float* __restrict__ b2,    // (10)
    float* __restrict__ out)         // (B,3)
{
    __shared__ __align__(16) float4 sTab[TABN][7];   // 28672 B
    __shared__ __align__(16) float4 sW2T[5][5];      // transposed pair layout
    __shared__ float sW1x[NIR], sW1y[NIR], sB1[NIR], sB2[NIR];

    const int tid = threadIdx.x;

    {
        const float4* src = &g_tab[0][0];
        float4* dst = &sTab[0][0];
        #pragma unroll
        for (int i = tid; i < TABN * 7; i += 256)
            dst[i] = src[i];
    }
    if (tid < 100){
        int u = tid / 10, v = tid % 10;
        reinterpret_cast<float*>(sW2T)[(v >> 1) * 20 + (u >> 1) * 4 + ((u & 1) << 1) + (v & 1)] = W2[tid];
    }
    if (tid < 10){
        sW1x[tid] = W1[tid];
        sW1y[tid] = W1[10 + tid];
        sB1[tid]  = b1[tid];
        sB2[tid]  = b2[tid];
    }
    __syncthreads();

    const int w    = tid >> 5;
    const int lane = tid & 31;
    const int b    = blockIdx.x * 8 + w;

    const size_t e0 = (size_t)b * 256 + lane;
    const float2* ivp = reinterpret_cast<const float2*>(invar) + e0;
    const float*  vb  = vec2 + e0 * 6;

    // ---- front-batch all global loads ----
    float2 iv[8];
    float  vx[8];
    float2 vyz[8];
    #pragma unroll
    for (int i = 0; i < 8; i++){
        iv[i]  = ivp[i * 32];
        const float* vp = vb + i * 192;           // 32*6
        vx[i]  = vp[3];
        vyz[i] = *reinterpret_cast<const float2*>(vp + 4);
    }

    uint64_t b2d[5];
    #pragma unroll
    for (int j = 0; j < 5; j++) b2d[j] = pack2(sB2[2*j], sB2[2*j+1]);

    float tx = 0.f, ty = 0.f, tz = 0.f;

    #pragma unroll
    for (int i = 0; i < 8; i++){
        // y1 = relu(invar @ W1 + b1), duplicated into f32x2 lanes
        uint64_t y1d[NIR];
        #pragma unroll
        for (int u = 0; u < NIR; u++){
            float y = fmaxf(fmaf(iv[i].x, sW1x[u], fmaf(iv[i].y, sW1y[u], sB1[u])), 0.0f);
            y1d[u] = pack2(y, y);
        }

        // y2 = relu(y1 @ W2 + b2): 50 fma2
        uint64_t y2d[NIR];
        #pragma unroll
        for (int j = 0; j < 5; j++){
            uint64_t acc = b2d[j];
            #pragma unroll
            for (int uu = 0; uu < 5; uu++){
                float4 wq = sW2T[j][uu];
                acc = fma2(y1d[2*uu],   lo64(wq), acc);
                acc = fma2(y1d[2*uu+1], hi64(wq), acc);
            }
            float2 rr = unpack2(acc);
            float m0 = fmaxf(rr.x, 0.0f);
            float m1 = fmaxf(rr.y, 0.0f);
            y2d[2*j]   = pack2(m0, m0);
            y2d[2*j+1] = pack2(m1, m1);
        }

        // r = |v|, table row k, dot with (a,b) pairs
        const float n2 = fmaf(vx[i], vx[i], fmaf(vyz[i].x, vyz[i].x, vyz[i].y * vyz[i].y));
        const float r  = sqrtaf(n2);
        int k = (int)(r * INV_DELTA);
        k = (k > TABN - 1) ? (TABN - 1) : k;

        const float4* row = sTab[k];
        uint64_t acc = 0ull;
        #pragma unroll
        for (int j = 0; j < 5; j++){
            float4 t = row[j];
            acc = fma2(y2d[2*j],   lo64(t), acc);
            acc = fma2(y2d[2*j+1], hi64(t), acc);
        }
        float2 sab = unpack2(acc);
        const float S = fmaf(r, sab.y, sab.x);

        tx = fmaf(vx[i],    S, tx);
        ty = fmaf(vyz[i].x, S, ty);
        tz = fmaf(vyz[i].y, S, tz);
    }

    // warp reduction (warp owns batch b entirely)
    #pragma unroll
    for (int off = 16; off > 0; off >>= 1){
        tx += __shfl_down_sync(0xFFFFFFFFu, tx, off);
        ty += __shfl_down_sync(0xFFFFFFFFu, ty, off);
        tz += __shfl_down_sync(0xFFFFFFFFu, tz, off);
    }
    if (lane == 0){
        const float a0 = v1b[b*3+0], a1 = v1b[b*3+1], a2 = v1b[b*3+2];
        out[b*3+0] = a1 * tz - a2 * ty;
        out[b*3+1] = a2 * tx - a0 * tz;
        out[b*3+2] = a0 * ty - a1 * tx;
    }
}

extern "C" void kernel_launch(void* const* d_in, const int* in_sizes, int n_in,
                              void* d_out, int out_size)
{
    const float* v1b   = (const float*)d_in[0];
    const float* invar = (const float*)d_in[1];
    const float* vec2  = (const float*)d_in[2];
    const float* W1    = (const float*)d_in[3];
    const float* b1    = (const float*)d_in[4];
    const float* W2    = (const float*)d_in[5];
    const float* b2    = (const float*)d_in[6];
    const float* lw1   = (const float*)d_in[7];
    const float* nb1   = (const float*)d_in[8];
    const float* lw2   = (const float*)d_in[9];
    const float* nb2   = (const float*)d_in[10];
    const float* wf    = (const float*)d_in[11];

    const int B = out_size / 3;   // 4096

    build_table<<<2, 128>>>(lw1, nb1, lw2, nb2, wf);
    trq_2b_kernel<<<B / 8, 256>>>(v1b, invar, vec2, W1, b1, W2, b2, (float*)d_out);
}

// round 8
// speedup vs baseline: 1.9653x; 1.0015x over previous
#include <cuda_runtime.h>
#include <cstdint>
#include <math.h>

#define NIR 10
#define EPS2 1e-12f
#define INV_SQRT10 0.31622776601683794f

#define TABN 256
#define RMAX 8.0f
#define DELTA (RMAX / (float)TABN)
#define INV_DELTA ((float)TABN / RMAX)

// coefficient table: h_v(r) ~= a_v + b_v*r on interval k.
// row layout: 7 x float4; j in 0..4 holds (a_{2j}, b_{2j}, a_{2j+1}, b_{2j+1}); j=5,6 pad.
__device__ __align__(16) float4 g_tab[TABN][7];

// weights in constant memory: [0..99] W2T pair-quads, [100..109] W1x,
// [110..119] W1y, [120..129] b1, [130..139] b2
__constant__ __align__(16) float cParams[144];
__device__  __align__(16) float g_stage[144];

static __device__ __forceinline__ float ex2f(float x){ float r; asm("ex2.approx.f32 %0, %1;" : "=f"(r) : "f"(x)); return r; }
static __device__ __forceinline__ float rcpf(float x){ float r; asm("rcp.approx.f32 %0, %1;" : "=f"(r) : "f"(x)); return r; }
static __device__ __forceinline__ float rsqf(float x){ float r; asm("rsqrt.approx.f32 %0, %1;" : "=f"(r) : "f"(x)); return r; }
static __device__ __forceinline__ float sqrtaf(float x){ float r; asm("sqrt.approx.f32 %0, %1;" : "=f"(r) : "f"(x)); return r; }

static __device__ __forceinline__ float tanh_fast(float z){
    float e = ex2f(z * 2.8853900817779268f);
    float r = rcpf(e + 1.0f);
    return fmaf(-2.0f, r, 1.0f);
}

static __device__ __forceinline__ uint64_t pack2(float lo, float hi){
    uint64_t r; asm("mov.b64 %0, {%1, %2};" : "=l"(r) : "f"(lo), "f"(hi)); return r;
}
static __device__ __forceinline__ float2 unpack2(uint64_t v){
    float2 f; asm("mov.b64 {%0, %1}, %2;" : "=f"(f.x), "=f"(f.y) : "l"(v)); return f;
}
static __device__ __forceinline__ uint64_t fma2(uint64_t a, uint64_t b, uint64_t c){
    uint64_t d; asm("fma.rn.f32x2 %0, %1, %2, %3;" : "=l"(d) : "l"(a), "l"(b), "l"(c)); return d;
}
static __device__ __forceinline__ uint64_t lo64(float4 w){ return pack2(w.x, w.y); }
static __device__ __forceinline__ uint64_t hi64(float4 w){ return pack2(w.z, w.w); }

// ---------------- table build + weight staging ----------------
static __device__ void eval_h(float r,
                              const float* __restrict__ lw1, const float* __restrict__ nb1,
                              const float* __restrict__ lw2, const float* __restrict__ nb2,
                              const float* __restrict__ wf, float* h)
{
    float n2 = r * r;
    float g[NIR];
    #pragma unroll
    for (int u = 0; u < NIR; u++){
        float a   = lw1[u];
        float arg = fmaf(a * a, n2, EPS2);
        float inv = rsqf(arg);
        float nrm = arg * inv;
        g[u] = tanh_fast(nrm + nb1[u]) * inv;
    }
    #pragma unroll
    for (int v = 0; v < NIR; v++){
        float c = 0.0f;
        #pragma unroll
        for (int u = 0; u < NIR; u++)
            c = fmaf(g[u] * lw1[u], lw2[u * NIR + v], c);
        c *= INV_SQRT10;
        float arg = fmaf(c * c, n2, EPS2);
        float inv = rsqf(arg);
        float nrm = arg * inv;
        float scal2 = tanh_fast(nrm + nb2[v]) * inv;
        h[v] = c * scal2 * wf[v] * INV_SQRT10;
    }
}

__global__ void build_table(const float* __restrict__ lw1, const float* __restrict__ nb1,
                            const float* __restrict__ lw2, const float* __restrict__ nb2,
                            const float* __restrict__ wf,
                            const float* __restrict__ W1, const float* __restrict__ b1,
                            const float* __restrict__ W2, const float* __restrict__ b2)
{
    int k = threadIdx.x;   // 0..255

    // stage permuted weights
    if (k < 100){
        int u = k / 10, v = k % 10;
        g_stage[(v >> 1) * 20 + (u >> 1) * 4 + ((u & 1) << 1) + (v & 1)] = W2[k];
    } else if (k < 110) g_stage[k] = W1[k - 100];
    else if (k < 120)   g_stage[k] = W1[k - 110 + 10];
    else if (k < 130)   g_stage[k] = b1[k - 120];
    else if (k < 140)   g_stage[k] = b2[k - 130];
    else if (k < 144)   g_stage[k] = 0.0f;

    if (k >= TABN) return;
    float r0 = (float)k * DELTA;
    float h0[NIR], h1[NIR];
    eval_h(r0,         lw1, nb1, lw2, nb2, wf, h0);
    eval_h(r0 + DELTA, lw1, nb1, lw2, nb2, wf, h1);
    #pragma unroll
    for (int j = 0; j < 5; j++){
        float bb0 = (h1[2*j]   - h0[2*j])   * INV_DELTA;
        float bb1 = (h1[2*j+1] - h0[2*j+1]) * INV_DELTA;
        float aa0 = fmaf(-bb0, r0, h0[2*j]);
        float aa1 = fmaf(-bb1, r0, h0[2*j+1]);
        g_tab[k][j] = make_float4(aa0, bb0, aa1, bb1);
    }
    g_tab[k][5] = make_float4(0.f, 0.f, 0.f, 0.f);
    g_tab[k][6] = make_float4(0.f, 0.f, 0.f, 0.f);
}

// ---------------- main kernel: persistent, warp-per-batch, W2 in constant ----------------
__global__ __launch_bounds__(256, 2) void trq_2b_kernel(
    const float* __restrict__ v1b,   // (B,3)
    const float* __restrict__ invar, // (B,P,2)
    const float* __restrict__ vec2,  // (B,P,6)
    float* __restrict__ out,         // (B,3)
    int nGroups)
{
    __shared__ __align__(16) float4 sTab[TABN][7];   // 28672 B

    const int tid = threadIdx.x;

    {
        const float4* src = &g_tab[0][0];
        float4* dst = &sTab[0][0];
        #pragma unroll
        for (int i = tid; i < TABN * 7; i += 256)
            dst[i] = src[i];
    }
    __syncthreads();

    const int w    = tid >> 5;
    const int lane = tid & 31;
    const float4* cW2q = reinterpret_cast<const float4*>(cParams);

    // hoist scalar weights (30 regs) and b2 pairs (10 regs)
    float w1x[NIR], w1y[NIR], bb1[NIR];
    #pragma unroll
    for (int u = 0; u < NIR; u++){
        w1x[u] = cParams[100 + u];
        w1y[u] = cParams[110 + u];
        bb1[u] = cParams[120 + u];
    }
    uint64_t b2d[5];
    #pragma unroll
    for (int j = 0; j < 5; j++) b2d[j] = pack2(cParams[130 + 2*j], cParams[131 + 2*j]);

    for (int g = blockIdx.x; g < nGroups; g += gridDim.x){
        const int b = g * 8 + w;

        const size_t e0 = (size_t)b * 256 + lane;
        const float2* ivp = reinterpret_cast<const float2*>(invar) + e0;
        const float*  vb  = vec2 + e0 * 6;

        // ---- front-batch all global loads ----
        float2 iv[8];
        float  vx[8];
        float2 vyz[8];
        #pragma unroll
        for (int i = 0; i < 8; i++){
            iv[i]  = ivp[i * 32];
            const float* vp = vb + i * 192;           // 32*6
            vx[i]  = vp[3];
            vyz[i] = *reinterpret_cast<const float2*>(vp + 4);
        }

        float tx = 0.f, ty = 0.f, tz = 0.f;

        #pragma unroll
        for (int i = 0; i < 8; i++){
            // y1 = relu(invar @ W1 + b1), duplicated into f32x2 lanes
            uint64_t y1d[NIR];
            #pragma unroll
            for (int u = 0; u < NIR; u++){
                float y = fmaxf(fmaf(iv[i].x, w1x[u], fmaf(iv[i].y, w1y[u], bb1[u])), 0.0f);
                y1d[u] = pack2(y, y);
            }

            // y2 = relu(y1 @ W2 + b2): W2 quads from CONSTANT port (no smem crossbar)
            uint64_t y2d[NIR];
            #pragma unroll
            for (int j = 0; j < 5; j++){
                uint64_t acc = b2d[j];
                #pragma unroll
                for (int uu = 0; uu < 5; uu++){
                    float4 wq = cW2q[j * 5 + uu];
                    acc = fma2(y1d[2*uu],   lo64(wq), acc);
                    acc = fma2(y1d[2*uu+1], hi64(wq), acc);
                }
                float2 rr = unpack2(acc);
                float m0 = fmaxf(rr.x, 0.0f);
                float m1 = fmaxf(rr.y, 0.0f);
                y2d[2*j]   = pack2(m0, m0);
                y2d[2*j+1] = pack2(m1, m1);
            }

            // r = |v|, table row k, dot with (a,b) pairs — two parallel acc chains
            const float n2 = fmaf(vx[i], vx[i], fmaf(vyz[i].x, vyz[i].x, vyz[i].y * vyz[i].y));
            const float r  = sqrtaf(n2);
            int k = (int)(r * INV_DELTA);
            k = (k > TABN - 1) ? (TABN - 1) : k;

            const float4* row = sTab[k];
            uint64_t acc0 = 0ull, acc1 = 0ull;
            #pragma unroll
            for (int j = 0; j < 5; j++){
                float4 t = row[j];
                if (j & 1){
                    acc1 = fma2(y2d[2*j],   lo64(t), acc1);
                    acc1 = fma2(y2d[2*j+1], hi64(t), acc1);
                } else {
                    acc0 = fma2(y2d[2*j],   lo64(t), acc0);
                    acc0 = fma2(y2d[2*j+1], hi64(t), acc0);
                }
            }
            float2 s0 = unpack2(acc0);
            float2 s1 = unpack2(acc1);
            const float S = fmaf(r, s0.y + s1.y, s0.x + s1.x);

            tx = fmaf(vx[i],    S, tx);
            ty = fmaf(vyz[i].x, S, ty);
            tz = fmaf(vyz[i].y, S, tz);
        }

        // warp reduction (warp owns batch b entirely)
        #pragma unroll
        for (int off = 16; off > 0; off >>= 1){
            tx += __shfl_down_sync(0xFFFFFFFFu, tx, off);
            ty += __shfl_down_sync(0xFFFFFFFFu, ty, off);
            tz += __shfl_down_sync(0xFFFFFFFFu, tz, off);
        }
        if (lane == 0){
            const float a0 = v1b[b*3+0], a1 = v1b[b*3+1], a2 = v1b[b*3+2];
            out[b*3+0] = a1 * tz - a2 * ty;
            out[b*3+1] = a2 * tx - a0 * tz;
            out[b*3+2] = a0 * ty - a1 * tx;
        }
    }
}

extern "C" void kernel_launch(void* const* d_in, const int* in_sizes, int n_in,
                              void* d_out, int out_size)
{
    const float* v1b   = (const float*)d_in[0];
    const float* invar = (const float*)d_in[1];
    const float* vec2  = (const float*)d_in[2];
    const float* W1    = (const float*)d_in[3];
    const float* b1    = (const float*)d_in[4];
    const float* W2    = (const float*)d_in[5];
    const float* b2    = (const float*)d_in[6];
    const float* lw1   = (const float*)d_in[7];
    const float* nb1   = (const float*)d_in[8];
    const float* lw2   = (const float*)d_in[9];
    const float* nb2   = (const float*)d_in[10];
    const float* wf    = (const float*)d_in[11];

    const int B = out_size / 3;        // 4096
    const int nGroups = B / 8;         // 512

    build_table<<<1, 256>>>(lw1, nb1, lw2, nb2, wf, W1, b1, W2, b2);

    void* stage_ptr = nullptr;
    cudaGetSymbolAddress(&stage_ptr, g_stage);
    cudaMemcpyToSymbolAsync(cParams, stage_ptr, 144 * sizeof(float), 0,
                            cudaMemcpyDeviceToDevice, 0);

    int grid = 304;                    // 2 blocks/SM x 152 SMs, wave-perfect
    if (grid > nGroups) grid = nGroups;
    trq_2b_kernel<<<grid, 256>>>(v1b, invar, vec2, (float*)d_out, nGroups);
}